// round 1
// baseline (speedup 1.0000x reference)
#include <cuda_runtime.h>
#include <math.h>
#include <stdint.h>

// Problem constants
#define BB    8
#define NN    2048
#define DD    512
#define MROWS (BB * NN)          // 16384
#define MW    1024               // concat width: [KV(512) | KW(512)]

// -------- scratch (static __device__, no allocation) --------
static __device__ float g_XT[DD * MROWS];          // [512][16384]  X^T
static __device__ float g_WT[3 * DD * DD];         // W^T for q,k,v
static __device__ float g_Q [MROWS * DD];
static __device__ float g_K [MROWS * DD];
static __device__ float g_V [MROWS * DD];
static __device__ float g_M [BB * NN * MW];        // [b][i][ exp(K)*V | exp(K) ]
static __device__ float g_W [BB * NN * MW];        // [b][j][ W1 | W2 ]

// ---------------- transpose: out[c][r] = in[r][c] ----------------
__global__ void transpose_kernel(const float* __restrict__ in,
                                 float* __restrict__ out,
                                 int rows, int cols) {
    __shared__ float tile[32][33];
    int c = blockIdx.x * 32 + threadIdx.x;
    int r = blockIdx.y * 32 + threadIdx.y;
#pragma unroll
    for (int j = 0; j < 32; j += 8)
        tile[threadIdx.y + j][threadIdx.x] = in[(size_t)(r + j) * cols + c];
    __syncthreads();
    int oc = blockIdx.y * 32 + threadIdx.x;   // out col = in row
    int orow = blockIdx.x * 32 + threadIdx.y; // out row = in col
#pragma unroll
    for (int j = 0; j < 32; j += 8)
        out[(size_t)(orow + j) * rows + oc] = tile[threadIdx.x][threadIdx.y + j];
}

// ---------------- GEMM (TN form): C[m,n] = sum_k A[k,m] * B[k,n] ----------------
// mode 0: A used as-is.  mode 1: A element a -> expf(-11*alpha*a)
// All tile dims divide exactly: BM=BN=128, BK=16, 256 threads, 8x8 per thread.
__global__ __launch_bounds__(256, 2)
void gemm_tn_kernel(const float* __restrict__ A, int lda,
                    const float* __restrict__ B, int ldb,
                    float* __restrict__ C, int ldc,
                    int K, int mode, const float* __restrict__ alphaPtr,
                    size_t strideA, size_t strideB, size_t strideC) {
    __shared__ float As[16][128];
    __shared__ float Bs[16][128];

    A += (size_t)blockIdx.z * strideA;
    B += (size_t)blockIdx.z * strideB;
    C += (size_t)blockIdx.z * strideC;

    const int m0 = blockIdx.y * 128;
    const int n0 = blockIdx.x * 128;

    float scale = 0.f;
    if (mode) scale = 11.0f * (*alphaPtr);   // log2(2048) = 11 exactly

    const int t   = threadIdx.x;
    const int tx  = t & 15;        // n micro-tile
    const int ty  = t >> 4;        // m micro-tile
    const int lr  = t >> 5;        // load row  (0..7)
    const int lc4 = (t & 31) * 4;  // load col  (float4)

    float acc[8][8];
#pragma unroll
    for (int i = 0; i < 8; ++i)
#pragma unroll
        for (int j = 0; j < 8; ++j) acc[i][j] = 0.f;

    for (int k0 = 0; k0 < K; k0 += 16) {
#pragma unroll
        for (int p = 0; p < 2; ++p) {
            int kk = lr + p * 8;
            float4 va = *(const float4*)&A[(size_t)(k0 + kk) * lda + m0 + lc4];
            float4 vb = *(const float4*)&B[(size_t)(k0 + kk) * ldb + n0 + lc4];
            if (mode) {
                va.x = __expf(-scale * va.x);
                va.y = __expf(-scale * va.y);
                va.z = __expf(-scale * va.z);
                va.w = __expf(-scale * va.w);
            }
            *(float4*)&As[kk][lc4] = va;
            *(float4*)&Bs[kk][lc4] = vb;
        }
        __syncthreads();
#pragma unroll
        for (int kk = 0; kk < 16; ++kk) {
            float a[8], b[8];
            *(float4*)(a)     = *(const float4*)&As[kk][ty * 8];
            *(float4*)(a + 4) = *(const float4*)&As[kk][ty * 8 + 4];
            *(float4*)(b)     = *(const float4*)&Bs[kk][tx * 8];
            *(float4*)(b + 4) = *(const float4*)&Bs[kk][tx * 8 + 4];
#pragma unroll
            for (int i = 0; i < 8; ++i)
#pragma unroll
                for (int j = 0; j < 8; ++j)
                    acc[i][j] += a[i] * b[j];
        }
        __syncthreads();
    }

#pragma unroll
    for (int i = 0; i < 8; ++i) {
        int m = m0 + ty * 8 + i;
#pragma unroll
        for (int j = 0; j < 8; j += 4) {
            float4 v = make_float4(acc[i][j], acc[i][j + 1], acc[i][j + 2], acc[i][j + 3]);
            *(float4*)&C[(size_t)m * ldc + n0 + tx * 8 + j] = v;
        }
    }
}

// ---------------- elementwise: build M = [ exp(K)*V | exp(K) ] ----------------
__global__ void ew_kv_kernel(const float* __restrict__ Kb,
                             const float* __restrict__ Vb,
                             float* __restrict__ M) {
    int idx = blockIdx.x * blockDim.x + threadIdx.x;   // over MROWS*DD
    if (idx >= MROWS * DD) return;
    int row = idx >> 9;          // /512
    int c   = idx & 511;
    float e = __expf(Kb[idx]);
    float v = Vb[idx];
    size_t o = (size_t)row * MW + c;
    M[o]       = e * v;
    M[o + 512] = e;
}

// ---------------- elementwise: out = sigmoid(Q) * W1/W2 ----------------
__global__ void ew_out_kernel(const float* __restrict__ Q,
                              const float* __restrict__ W,
                              float* __restrict__ out) {
    int idx = blockIdx.x * blockDim.x + threadIdx.x;
    if (idx >= MROWS * DD) return;
    int row = idx >> 9;
    int c   = idx & 511;
    float q  = Q[idx];
    float sg = 1.f / (1.f + __expf(-q));
    size_t o = (size_t)row * MW + c;
    float w1 = W[o];
    float w2 = W[o + 512];
    out[idx] = sg * w1 / w2;
}

// ---------------- launcher ----------------
extern "C" void kernel_launch(void* const* d_in, const int* in_sizes, int n_in,
                              void* d_out, int out_size) {
    const float* x     = (const float*)d_in[0];   // [8,2048,512]
    const float* dis   = (const float*)d_in[1];   // [8,2048,2048]
    const float* Wq    = (const float*)d_in[2];   // [512,512]
    const float* Wk    = (const float*)d_in[3];
    const float* Wv    = (const float*)d_in[4];
    const float* alpha = (const float*)d_in[5];   // scalar
    float* out = (float*)d_out;

    float *pXT, *pWT, *pQ, *pK, *pV, *pM, *pW;
    cudaGetSymbolAddress((void**)&pXT, g_XT);
    cudaGetSymbolAddress((void**)&pWT, g_WT);
    cudaGetSymbolAddress((void**)&pQ,  g_Q);
    cudaGetSymbolAddress((void**)&pK,  g_K);
    cudaGetSymbolAddress((void**)&pV,  g_V);
    cudaGetSymbolAddress((void**)&pM,  g_M);
    cudaGetSymbolAddress((void**)&pW,  g_W);

    dim3 tb(32, 8);
    // X^T : [16384,512] -> [512,16384]
    transpose_kernel<<<dim3(DD / 32, MROWS / 32), tb>>>(x, pXT, MROWS, DD);
    // W^T for q,k,v
    transpose_kernel<<<dim3(DD / 32, DD / 32), tb>>>(Wq, pWT + 0 * DD * DD, DD, DD);
    transpose_kernel<<<dim3(DD / 32, DD / 32), tb>>>(Wk, pWT + 1 * DD * DD, DD, DD);
    transpose_kernel<<<dim3(DD / 32, DD / 32), tb>>>(Wv, pWT + 2 * DD * DD, DD, DD);

    // Q/K/V = X @ W^T  ==  C[m,n] = sum_k XT[k,m] * WT[k,n]
    dim3 gqkv(DD / 128, MROWS / 128, 1);
    gemm_tn_kernel<<<gqkv, 256>>>(pXT, MROWS, pWT + 0 * DD * DD, DD, pQ, DD,
                                  DD, 0, nullptr, 0, 0, 0);
    gemm_tn_kernel<<<gqkv, 256>>>(pXT, MROWS, pWT + 1 * DD * DD, DD, pK, DD,
                                  DD, 0, nullptr, 0, 0, 0);
    gemm_tn_kernel<<<gqkv, 256>>>(pXT, MROWS, pWT + 2 * DD * DD, DD, pV, DD,
                                  DD, 0, nullptr, 0, 0, 0);

    // M = [ exp(K)*V | exp(K) ]
    ew_kv_kernel<<<(MROWS * DD) / 256, 256>>>(pK, pV, pM);

    // per-batch: W[j,c] = sum_i exp(-11a*dis[b,i,j]) * M[b,i,c]
    dim3 ge(MW / 128, NN / 128, BB);
    gemm_tn_kernel<<<ge, 256>>>(dis, NN, pM, MW, pW, MW,
                                NN, 1, alpha,
                                (size_t)NN * NN, (size_t)NN * MW, (size_t)NN * MW);

    // out = sigmoid(Q) * W1/W2
    ew_out_kernel<<<(MROWS * DD) / 256, 256>>>(pQ, pW, out);
}

// round 4
// speedup vs baseline: 2.0583x; 2.0583x over previous
#include <cuda_runtime.h>
#include <cuda_bf16.h>
#include <stdint.h>

// ---------------- problem constants ----------------
#define BB    8
#define NND   2048
#define DDIM  512
#define MROWS (BB * NND)     // 16384
#define MW    1024           // [expK*V | expK]

// ---------------- scratch (static device, no allocation) ----------------
static __device__ __align__(256) __nv_bfloat16 g_Xhi[MROWS * DDIM];
static __device__ __align__(256) __nv_bfloat16 g_Xlo[MROWS * DDIM];
static __device__ __align__(256) __nv_bfloat16 g_Whi[3 * DDIM * DDIM];
static __device__ __align__(256) __nv_bfloat16 g_Wlo[3 * DDIM * DDIM];
static __device__ __align__(256) float         g_QKV[3 * MROWS * DDIM];
static __device__ __align__(256) __nv_bfloat16 g_Ahi[(size_t)BB * NND * NND];
static __device__ __align__(256) __nv_bfloat16 g_Alo[(size_t)BB * NND * NND];
static __device__ __align__(256) __nv_bfloat16 g_Bhi[(size_t)BB * MW * NND];
static __device__ __align__(256) __nv_bfloat16 g_Blo[(size_t)BB * MW * NND];
static __device__ __align__(256) float         g_Wout[(size_t)BB * NND * MW];

// ---------------- helpers ----------------
static __device__ __forceinline__ void split2(float a, __nv_bfloat16& hi, __nv_bfloat16& lo) {
    hi = __float2bfloat16(a);
    lo = __float2bfloat16(a - __bfloat162float(hi));
}
static __device__ __forceinline__ uint32_t smem_u32(const void* p) {
    uint32_t a;
    asm("{ .reg .u64 t; cvta.to.shared.u64 t, %1; cvt.u32.u64 %0, t; }" : "=r"(a) : "l"(p));
    return a;
}
static __device__ __forceinline__ void cp16(uint32_t dst, const void* src) {
    asm volatile("cp.async.cg.shared.global [%0], [%1], 16;" :: "r"(dst), "l"(src));
}
static __device__ __forceinline__ uint32_t lds32(uint32_t a) {
    uint32_t v;
    asm volatile("ld.shared.b32 %0, [%1];" : "=r"(v) : "r"(a));
    return v;
}
#define MMA(d, a, b)                                                          \
    asm volatile(                                                             \
        "mma.sync.aligned.m16n8k16.row.col.f32.bf16.bf16.f32 "                \
        "{%0,%1,%2,%3}, {%4,%5,%6,%7}, {%8,%9}, {%0,%1,%2,%3};"               \
        : "+f"(d[0]), "+f"(d[1]), "+f"(d[2]), "+f"(d[3])                      \
        : "r"(a[0]), "r"(a[1]), "r"(a[2]), "r"(a[3]), "r"(b[0]), "r"(b[1]))

// ---------------- P1: fp32 -> bf16 hi/lo split ----------------
__global__ void split_kernel(const float* __restrict__ src,
                             __nv_bfloat16* __restrict__ hi,
                             __nv_bfloat16* __restrict__ lo, int n) {
    int i = blockIdx.x * blockDim.x + threadIdx.x;
    if (i >= n) return;
    __nv_bfloat16 h, l;
    split2(src[i], h, l);
    hi[i] = h; lo[i] = l;
}

// ---------------- P2: Ahi/Alo[b][j][i] = split(exp(-s*dis[b][i][j])) ----------------
__global__ void prepA_kernel(const float* __restrict__ dis,
                             const float* __restrict__ alphaPtr,
                             __nv_bfloat16* __restrict__ Ahi,
                             __nv_bfloat16* __restrict__ Alo) {
    __shared__ float tile[32][33];
    const float s = 11.0f * alphaPtr[0];   // log2(2048) = 11
    int b = blockIdx.z;
    int j0 = blockIdx.x * 32, i0 = blockIdx.y * 32;
    const float* D = dis + (size_t)b * NND * NND;
#pragma unroll
    for (int jj = 0; jj < 32; jj += 8) {
        float d = D[(size_t)(i0 + threadIdx.y + jj) * NND + j0 + threadIdx.x];
        tile[threadIdx.y + jj][threadIdx.x] = __expf(-s * d);
    }
    __syncthreads();
    size_t ob = (size_t)b * NND * NND;
#pragma unroll
    for (int jj = 0; jj < 32; jj += 8) {
        float w = tile[threadIdx.x][threadIdx.y + jj];
        __nv_bfloat16 h, l; split2(w, h, l);
        size_t o = ob + (size_t)(j0 + threadIdx.y + jj) * NND + i0 + threadIdx.x;
        Ahi[o] = h; Alo[o] = l;
    }
}

// ---------------- P3: Bhi/Blo[b][c][i]: c<512: expK*V ; c>=512: expK ----------------
__global__ void prepB_kernel(const float* __restrict__ Kmat,
                             const float* __restrict__ Vmat,
                             __nv_bfloat16* __restrict__ Bhi,
                             __nv_bfloat16* __restrict__ Blo) {
    __shared__ float tkv[32][33];
    __shared__ float tk[32][33];
    int b = blockIdx.z;
    int d0 = blockIdx.x * 32, i0 = blockIdx.y * 32;
#pragma unroll
    for (int jj = 0; jj < 32; jj += 8) {
        size_t r = (size_t)(b * NND + i0 + threadIdx.y + jj) * DDIM + d0 + threadIdx.x;
        float e = __expf(Kmat[r]);
        tk[threadIdx.y + jj][threadIdx.x] = e;
        tkv[threadIdx.y + jj][threadIdx.x] = e * Vmat[r];
    }
    __syncthreads();
    size_t ob = (size_t)b * MW * NND;
#pragma unroll
    for (int jj = 0; jj < 32; jj += 8) {
        int c = d0 + threadIdx.y + jj;
        int i = i0 + threadIdx.x;
        float kv = tkv[threadIdx.x][threadIdx.y + jj];
        float k  = tk [threadIdx.x][threadIdx.y + jj];
        __nv_bfloat16 h, l;
        size_t o1 = ob + (size_t)c * NND + i;
        split2(kv, h, l); Bhi[o1] = h; Blo[o1] = l;
        size_t o2 = ob + (size_t)(c + 512) * NND + i;
        split2(k, h, l);  Bhi[o2] = h; Blo[o2] = l;
    }
}

// ---------------- bf16-split HMMA GEMM ----------------
// C[m,n] = sum_k A[m,k]*B[n,k], operands K-major bf16 hi/lo (row stride Kdim).
// CTA 128x128, BK=32, 8 warps of 64x32, 3-stage cp.async pipeline.
#define STRIDE  40                 // padded bf16 row stride (conflict-free)
#define MATB    (128 * STRIDE * 2) // 10240 bytes per matrix
#define STAGEB  (4 * MATB)         // 40960
#define NSTAGE  3
#define SMEMSZ  (NSTAGE * STAGEB)  // 122880

__global__ __launch_bounds__(256, 1)
void gemm_mma_kernel(const __nv_bfloat16* __restrict__ Ahi,
                     const __nv_bfloat16* __restrict__ Alo, size_t sA,
                     const __nv_bfloat16* __restrict__ Bhi,
                     const __nv_bfloat16* __restrict__ Blo, size_t sB,
                     float* __restrict__ C, int ldC, size_t sC, int Kdim) {
    extern __shared__ char smem[];
    const uint32_t sbase = smem_u32(smem);
    const int t    = threadIdx.x;
    const int lane = t & 31;
    const int wid  = t >> 5;
    const int wm   = (wid >> 2) * 64;   // warp m-offset in tile
    const int wn   = (wid & 3) * 32;    // warp n-offset in tile
    const int g    = lane >> 2;
    const int i2   = (lane & 3) * 2;

    const size_t z = blockIdx.z;
    const __nv_bfloat16* srcs[4] = { Ahi + z * sA, Alo + z * sA,
                                     Bhi + z * sB, Blo + z * sB };
    const int m0 = blockIdx.y * 128;
    const int n0 = blockIdx.x * 128;
    const int rb[4] = { m0, m0, n0, n0 };

    const int nc = Kdim >> 5;   // k-chunks of 32

    // ---- stage loader: 2 chunks of 16B per thread per matrix ----
    auto load_stage = [&](int s, int k0) {
        uint32_t sdst = sbase + s * STAGEB;
#pragma unroll
        for (int mat = 0; mat < 4; ++mat) {
            const __nv_bfloat16* src = srcs[mat];
            int rbase = rb[mat];
#pragma unroll
            for (int r = 0; r < 2; ++r) {
                int chunk = r * 256 + t;
                int row = chunk >> 2;
                int c16 = chunk & 3;
                const void* gp = src + (size_t)(rbase + row) * Kdim + k0 + c16 * 8;
                cp16(sdst + mat * MATB + row * (STRIDE * 2) + c16 * 16, gp);
            }
        }
        asm volatile("cp.async.commit_group;");
    };

    float acc[4][4][4];
#pragma unroll
    for (int mi = 0; mi < 4; ++mi)
#pragma unroll
        for (int ni = 0; ni < 4; ++ni)
#pragma unroll
            for (int r = 0; r < 4; ++r) acc[mi][ni][r] = 0.f;

    load_stage(0, 0);
    load_stage(1, 32);

    for (int c = 0; c < nc; ++c) {
        asm volatile("cp.async.wait_group 1;");
        __syncthreads();
        if (c + 2 < nc) load_stage((c + 2) % NSTAGE, (c + 2) * 32);

        const uint32_t stg = sbase + (c % NSTAGE) * STAGEB;
#pragma unroll
        for (int kk = 0; kk < 32; kk += 16) {
            uint32_t Ah[4][4], Bh[4][2], Tm[4][4];
            // row addr helper offsets (bytes)
            const uint32_t kb = (kk + i2) * 2;
            // load Ah frags
#pragma unroll
            for (int mi = 0; mi < 4; ++mi) {
                uint32_t a = stg + ((wm + mi * 16 + g) * STRIDE) * 2 + kb;
                Ah[mi][0] = lds32(a);
                Ah[mi][1] = lds32(a + 8 * STRIDE * 2);
                Ah[mi][2] = lds32(a + 16);
                Ah[mi][3] = lds32(a + 8 * STRIDE * 2 + 16);
            }
            // load Bh frags
#pragma unroll
            for (int ni = 0; ni < 4; ++ni) {
                uint32_t b = stg + 2 * MATB + ((wn + ni * 8 + g) * STRIDE) * 2 + kb;
                Bh[ni][0] = lds32(b);
                Bh[ni][1] = lds32(b + 16);
            }
            // pass 1: Ah x Bh
#pragma unroll
            for (int mi = 0; mi < 4; ++mi)
#pragma unroll
                for (int ni = 0; ni < 4; ++ni) MMA(acc[mi][ni], Ah[mi], Bh[ni]);
            // pass 2: Ah x Bl
            uint32_t Bl[4][2];
#pragma unroll
            for (int ni = 0; ni < 4; ++ni) {
                uint32_t b = stg + 3 * MATB + ((wn + ni * 8 + g) * STRIDE) * 2 + kb;
                Bl[ni][0] = lds32(b);
                Bl[ni][1] = lds32(b + 16);
            }
#pragma unroll
            for (int mi = 0; mi < 4; ++mi)
#pragma unroll
                for (int ni = 0; ni < 4; ++ni) MMA(acc[mi][ni], Ah[mi], Bl[ni]);
            // pass 3: Al x Bh
#pragma unroll
            for (int mi = 0; mi < 4; ++mi) {
                uint32_t a = stg + MATB + ((wm + mi * 16 + g) * STRIDE) * 2 + kb;
                Tm[mi][0] = lds32(a);
                Tm[mi][1] = lds32(a + 8 * STRIDE * 2);
                Tm[mi][2] = lds32(a + 16);
                Tm[mi][3] = lds32(a + 8 * STRIDE * 2 + 16);
            }
#pragma unroll
            for (int mi = 0; mi < 4; ++mi)
#pragma unroll
                for (int ni = 0; ni < 4; ++ni) MMA(acc[mi][ni], Tm[mi], Bh[ni]);
        }
        __syncthreads();
    }

    // ---- epilogue: fp32 stores ----
    float* Cz = C + z * sC;
#pragma unroll
    for (int mi = 0; mi < 4; ++mi) {
        int row0 = m0 + wm + mi * 16 + g;
#pragma unroll
        for (int ni = 0; ni < 4; ++ni) {
            int col = n0 + wn + ni * 8 + i2;
            *(float2*)&Cz[(size_t)row0 * ldC + col] =
                make_float2(acc[mi][ni][0], acc[mi][ni][1]);
            *(float2*)&Cz[(size_t)(row0 + 8) * ldC + col] =
                make_float2(acc[mi][ni][2], acc[mi][ni][3]);
        }
    }
}

// ---------------- P4: out = sigmoid(Q) * W1/W2 ----------------
__global__ void ew_out_kernel(const float* __restrict__ Q,
                              const float* __restrict__ W,
                              float* __restrict__ out) {
    int idx = blockIdx.x * blockDim.x + threadIdx.x;
    if (idx >= MROWS * DDIM) return;
    int row = idx >> 9;
    int c   = idx & 511;
    float q  = Q[idx];
    float sg = 1.f / (1.f + __expf(-q));
    size_t o = (size_t)row * MW + c;
    out[idx] = sg * W[o] / W[o + 512];
}

// ---------------- launcher ----------------
extern "C" void kernel_launch(void* const* d_in, const int* in_sizes, int n_in,
                              void* d_out, int out_size) {
    const float* x     = (const float*)d_in[0];
    const float* dis   = (const float*)d_in[1];
    const float* Wq    = (const float*)d_in[2];
    const float* Wk    = (const float*)d_in[3];
    const float* Wv    = (const float*)d_in[4];
    const float* alpha = (const float*)d_in[5];
    float* out = (float*)d_out;

    __nv_bfloat16 *pXhi, *pXlo, *pWhi, *pWlo, *pAhi, *pAlo, *pBhi, *pBlo;
    float *pQKV, *pW;
    cudaGetSymbolAddress((void**)&pXhi, g_Xhi);
    cudaGetSymbolAddress((void**)&pXlo, g_Xlo);
    cudaGetSymbolAddress((void**)&pWhi, g_Whi);
    cudaGetSymbolAddress((void**)&pWlo, g_Wlo);
    cudaGetSymbolAddress((void**)&pQKV, g_QKV);
    cudaGetSymbolAddress((void**)&pAhi, g_Ahi);
    cudaGetSymbolAddress((void**)&pAlo, g_Alo);
    cudaGetSymbolAddress((void**)&pBhi, g_Bhi);
    cudaGetSymbolAddress((void**)&pBlo, g_Blo);
    cudaGetSymbolAddress((void**)&pW,  g_Wout);

    cudaFuncSetAttribute(gemm_mma_kernel,
                         cudaFuncAttributeMaxDynamicSharedMemorySize, SMEMSZ);

    // split X, Wq/Wk/Wv into bf16 hi/lo
    split_kernel<<<(MROWS * DDIM) / 256, 256>>>(x, pXhi, pXlo, MROWS * DDIM);
    split_kernel<<<(DDIM * DDIM) / 256, 256>>>(Wq, pWhi, pWlo, DDIM * DDIM);
    split_kernel<<<(DDIM * DDIM) / 256, 256>>>(Wk, pWhi + DDIM * DDIM, pWlo + DDIM * DDIM, DDIM * DDIM);
    split_kernel<<<(DDIM * DDIM) / 256, 256>>>(Wv, pWhi + 2 * DDIM * DDIM, pWlo + 2 * DDIM * DDIM, DDIM * DDIM);

    // QKV: C[m,n] = sum_k X[m,k] W[n,k]  (z selects Q/K/V weight + output)
    {
        dim3 g(DDIM / 128, MROWS / 128, 3);
        gemm_mma_kernel<<<g, 256, SMEMSZ>>>(
            pXhi, pXlo, (size_t)0,
            pWhi, pWlo, (size_t)DDIM * DDIM,
            pQKV, DDIM, (size_t)MROWS * DDIM, DDIM);
    }

    // prep A (exp(-s*dis) transposed + split) and B ([expK*V|expK] transposed + split)
    prepA_kernel<<<dim3(NND / 32, NND / 32, BB), dim3(32, 8)>>>(dis, alpha, pAhi, pAlo);
    prepB_kernel<<<dim3(DDIM / 32, NND / 32, BB), dim3(32, 8)>>>(
        pQKV + (size_t)1 * MROWS * DDIM, pQKV + (size_t)2 * MROWS * DDIM, pBhi, pBlo);

    // einsum: Wout[b][j][c] = sum_i expdisT[b][j][i] * MT[b][c][i]
    {
        dim3 g(MW / 128, NND / 128, BB);
        gemm_mma_kernel<<<g, 256, SMEMSZ>>>(
            pAhi, pAlo, (size_t)NND * NND,
            pBhi, pBlo, (size_t)MW * NND,
            pW, MW, (size_t)NND * MW, NND);
    }

    // out = sigmoid(Q) * W1/W2
    ew_out_kernel<<<(MROWS * DDIM) / 256, 256>>>(pQKV, pW, out);
}